// round 1
// baseline (speedup 1.0000x reference)
#include <cuda_runtime.h>
#include <math.h>

#define BB 2
#define NNTOK 2048
#define DD 1024
#define HH 16
#define HDIM 64
#define BN (BB*NNTOK)   /* 4096 rows */

// ---------------- scratch (device globals; no allocation allowed) ----------------
__device__ float g_q [BN*DD];
__device__ float g_k [BN*DD];
__device__ float g_v [BN*DD];
__device__ float g_f [BN*HH];   // f_t   = sigmoid(x @ Wf)      (scalar decay per head)
__device__ float g_g [BN*HH];   // sigmoid(x @ Wgamma)          (gamma = -this)
__device__ float g_g1[BN*HDIM]; // x @ Wg1 (raw)
__device__ float g_o [BN*DD];   // recurrence output
__device__ float g_n [BN*DD];   // gated + layernormed

__device__ __forceinline__ float sigmoidf_(float x) { return 1.f / (1.f + expf(-x)); }

// ---------------- generic fp32 SGEMM: C = act(A[MxK] @ B[KxN]) -------------------
// BM=BN=128, BK=16, 256 threads, 8x8 per thread. M%128==0, N%128==0, K%16==0.
__global__ __launch_bounds__(256) void sgemm_kernel(
    const float* __restrict__ A, const float* __restrict__ B, float* __restrict__ C,
    int M, int N, int K, int act)
{
    __shared__ float As[16][128];
    __shared__ float Bs[16][128];
    const int tid = threadIdx.x;
    const int tx  = tid & 15;
    const int ty  = tid >> 4;
    const int bn  = blockIdx.x;
    const int bm  = blockIdx.y;

    const int arow = tid >> 2;        // 0..63
    const int akc  = (tid & 3) * 4;   // 0,4,8,12
    const int brow = tid >> 5;        // 0..7
    const int bcol = (tid & 31) * 4;  // 0..124

    const float* Ab  = A + (size_t)(bm * 128 + arow) * K + akc;
    const float* Ab2 = Ab + (size_t)64 * K;
    const float* Bb  = B + (size_t)brow * N + bn * 128 + bcol;
    const float* Bb2 = Bb + (size_t)8 * N;

    float acc[8][8];
#pragma unroll
    for (int i = 0; i < 8; i++)
#pragma unroll
        for (int j = 0; j < 8; j++) acc[i][j] = 0.f;

    for (int k0 = 0; k0 < K; k0 += 16) {
        float4 a0 = *(const float4*)(Ab  + k0);
        float4 a1 = *(const float4*)(Ab2 + k0);
        float4 b0 = *(const float4*)(Bb  + (size_t)k0 * N);
        float4 b1 = *(const float4*)(Bb2 + (size_t)k0 * N);
        __syncthreads();
        As[akc + 0][arow] = a0.x; As[akc + 1][arow] = a0.y;
        As[akc + 2][arow] = a0.z; As[akc + 3][arow] = a0.w;
        As[akc + 0][arow + 64] = a1.x; As[akc + 1][arow + 64] = a1.y;
        As[akc + 2][arow + 64] = a1.z; As[akc + 3][arow + 64] = a1.w;
        *(float4*)&Bs[brow    ][bcol] = b0;
        *(float4*)&Bs[brow + 8][bcol] = b1;
        __syncthreads();
#pragma unroll
        for (int kk = 0; kk < 16; kk++) {
            float ar[8], br[8];
            *(float4*)(ar    ) = *(const float4*)&As[kk][ty * 8];
            *(float4*)(ar + 4) = *(const float4*)&As[kk][ty * 8 + 4];
            *(float4*)(br    ) = *(const float4*)&Bs[kk][tx * 8];
            *(float4*)(br + 4) = *(const float4*)&Bs[kk][tx * 8 + 4];
#pragma unroll
            for (int i = 0; i < 8; i++)
#pragma unroll
                for (int j = 0; j < 8; j++)
                    acc[i][j] = fmaf(ar[i], br[j], acc[i][j]);
        }
    }

    const int crow = bm * 128 + ty * 8;
    const int ccol = bn * 128 + tx * 8;
#pragma unroll
    for (int i = 0; i < 8; i++) {
        float v[8];
#pragma unroll
        for (int j = 0; j < 8; j++) {
            float z = acc[i][j];
            v[j] = act ? (z / (1.f + expf(-z))) : z;   // silu
        }
        *(float4*)&C[(size_t)(crow + i) * N + ccol    ] = *(float4*)(v);
        *(float4*)&C[(size_t)(crow + i) * N + ccol + 4] = *(float4*)(v + 4);
    }
}

// ---------- small projections: f = sig(x Wf), g = sig(x Wgamma), g1 = x Wg1 ------
// 32 rows per block, 96 threads (one per output column). Broadcast-LDS inner loop.
__global__ __launch_bounds__(96) void smallproj_kernel(
    const float* __restrict__ x,
    const float* __restrict__ Wgamma, const float* __restrict__ Wf,
    const float* __restrict__ Wg1)
{
    __shared__ float xs[32][64];
    const int row0 = blockIdx.x * 32;
    const int t = threadIdx.x;

    const float* W; int stride, c;
    if (t < 16)      { W = Wgamma; stride = 16; c = t; }
    else if (t < 32) { W = Wf;     stride = 16; c = t - 16; }
    else             { W = Wg1;    stride = 64; c = t - 32; }

    float acc[32];
#pragma unroll
    for (int r = 0; r < 32; r++) acc[r] = 0.f;

    for (int kt = 0; kt < DD; kt += 64) {
        __syncthreads();
        for (int i = t; i < 32 * 64; i += 96) {
            int r = i >> 6, kk = i & 63;
            xs[r][kk] = x[(size_t)(row0 + r) * DD + kt + kk];
        }
        __syncthreads();
#pragma unroll 4
        for (int kk = 0; kk < 64; kk++) {
            float wv = W[(size_t)(kt + kk) * stride + c];
#pragma unroll
            for (int r = 0; r < 32; r++) acc[r] = fmaf(xs[r][kk], wv, acc[r]);
        }
    }

    if (t < 16) {
#pragma unroll
        for (int r = 0; r < 32; r++) g_g[(size_t)(row0 + r) * HH + c] = sigmoidf_(acc[r]);
    } else if (t < 32) {
#pragma unroll
        for (int r = 0; r < 32; r++) g_f[(size_t)(row0 + r) * HH + c] = sigmoidf_(acc[r]);
    } else {
#pragma unroll
        for (int r = 0; r < 32; r++) g_g1[(size_t)(row0 + r) * HDIM + c] = acc[r];
    }
}

// ---------------- l2-normalize k per (b,n,h) over 64 dims ------------------------
__global__ __launch_bounds__(256) void l2norm_kernel()
{
    int hr   = blockIdx.x * 8 + (threadIdx.x >> 5);  // head-row 0..65535
    int lane = threadIdx.x & 31;
    float2* kp = (float2*)(g_k + (size_t)hr * HDIM);
    float2 v = kp[lane];
    float ss = v.x * v.x + v.y * v.y;
#pragma unroll
    for (int o = 16; o; o >>= 1) ss += __shfl_xor_sync(0xffffffffu, ss, o);
    float inv = 1.f / fmaxf(sqrtf(ss), 1e-12f);
    v.x *= inv; v.y *= inv;
    kp[lane] = v;
}

// ---------------- gated delta-rule recurrence ------------------------------------
// grid = 32 (b,h) * 4 colgroups = 128 blocks, 64 threads (2 warps).
// warp handles 8 Dv-columns; lane: col = base + (lane&7), rows (lane>>3)*16..+16.
// Step (f scalar, gamma scalar, k unit-norm):
//   d_j = k . S[:,j] ; u_j = -g f^2 d_j + v_j ; S = f S + k (x) u ; o_j = q . S[:,j]
__global__ __launch_bounds__(64) void recur_kernel()
{
    const int blk = blockIdx.x;
    const int bh  = blk >> 2;
    const int cg  = blk & 3;
    const int b   = bh >> 4;
    const int h   = bh & 15;
    const int w   = threadIdx.x >> 5;
    const int lane = threadIdx.x & 31;
    const int col = cg * 16 + w * 8 + (lane & 7);
    const int r0  = (lane >> 3) * 16;

    const size_t basev = (size_t)b * NNTOK * DD + h * HDIM;
    const float* kp = g_k + basev + r0;
    const float* qp = g_q + basev + r0;
    const float* vp = g_v + basev + col;
    float*       op = g_o + basev + col;
    const float* fp = g_f + (size_t)b * NNTOK * HH + h;
    const float* gp = g_g + (size_t)b * NNTOK * HH + h;

    float S[16];
#pragma unroll
    for (int i = 0; i < 16; i++) S[i] = 0.f;

    float4 kn[4], qn[4]; float vn, fn, gn;
#pragma unroll
    for (int i = 0; i < 4; i++) {
        kn[i] = *(const float4*)(kp + 4 * i);
        qn[i] = *(const float4*)(qp + 4 * i);
    }
    vn = *vp; fn = *fp; gn = *gp;

    for (int t = 0; t < NNTOK; t++) {
        float kc[16], qc[16];
#pragma unroll
        for (int i = 0; i < 4; i++) {
            kc[4*i] = kn[i].x; kc[4*i+1] = kn[i].y; kc[4*i+2] = kn[i].z; kc[4*i+3] = kn[i].w;
            qc[4*i] = qn[i].x; qc[4*i+1] = qn[i].y; qc[4*i+2] = qn[i].z; qc[4*i+3] = qn[i].w;
        }
        const float vc = vn, fc = fn, gc = gn;

        if (t < NNTOK - 1) { kp += DD; qp += DD; vp += DD; fp += HH; gp += HH; }
#pragma unroll
        for (int i = 0; i < 4; i++) {
            kn[i] = *(const float4*)(kp + 4 * i);
            qn[i] = *(const float4*)(qp + 4 * i);
        }
        vn = *vp; fn = *fp; gn = *gp;

        float d0 = 0.f, d1 = 0.f;
#pragma unroll
        for (int i = 0; i < 8; i++)  d0 = fmaf(kc[i], S[i], d0);
#pragma unroll
        for (int i = 8; i < 16; i++) d1 = fmaf(kc[i], S[i], d1);
        float d = d0 + d1;
        d += __shfl_xor_sync(0xffffffffu, d, 8);
        d += __shfl_xor_sync(0xffffffffu, d, 16);

        const float u = fmaf(-gc * fc * fc, d, vc);

        float o0 = 0.f, o1 = 0.f;
#pragma unroll
        for (int i = 0; i < 16; i++) {
            S[i] = fmaf(fc, S[i], kc[i] * u);
            float p = qc[i] * S[i];
            if (i < 8) o0 += p; else o1 += p;
        }
        float o = o0 + o1;
        o += __shfl_xor_sync(0xffffffffu, o, 8);
        o += __shfl_xor_sync(0xffffffffu, o, 16);

        if (lane < 8) op[(size_t)t * DD] = o;
    }
}

// --------- gate = sigmoid(g1 @ Wg2); out = o*gate; LayerNorm(weight) -------------
// 8 rows per block, 256 threads.
__global__ __launch_bounds__(256) void gate_ln_kernel(
    const float* __restrict__ Wg2, const float* __restrict__ nw)
{
    __shared__ float g1s[8 * 64];
    __shared__ float rb[8 * 1024];
    const int row0 = blockIdx.x * 8;
    const int tid = threadIdx.x;

    for (int i = tid; i < 512; i += 256) g1s[i] = g_g1[(size_t)row0 * 64 + i];
    __syncthreads();

#pragma unroll
    for (int cs = 0; cs < 4; cs++) {
        const int c = tid + cs * 256;
        float a[8];
#pragma unroll
        for (int r = 0; r < 8; r++) a[r] = 0.f;
#pragma unroll 4
        for (int k = 0; k < 64; k++) {
            float wv = Wg2[(size_t)k * DD + c];
#pragma unroll
            for (int r = 0; r < 8; r++) a[r] = fmaf(g1s[r * 64 + k], wv, a[r]);
        }
#pragma unroll
        for (int r = 0; r < 8; r++) {
            float gate = 1.f / (1.f + expf(-a[r]));
            rb[r * 1024 + c] = g_o[(size_t)(row0 + r) * DD + c] * gate;
        }
    }
    __syncthreads();

    const int wr = tid >> 5, ln = tid & 31;
    float s = 0.f, s2 = 0.f;
#pragma unroll 8
    for (int i = 0; i < 32; i++) {
        float v = rb[wr * 1024 + ln + 32 * i];
        s += v; s2 = fmaf(v, v, s2);
    }
#pragma unroll
    for (int o = 16; o; o >>= 1) {
        s  += __shfl_xor_sync(0xffffffffu, s,  o);
        s2 += __shfl_xor_sync(0xffffffffu, s2, o);
    }
    const float mu   = s * (1.f / 1024.f);
    const float var  = s2 * (1.f / 1024.f) - mu * mu;
    const float rstd = rsqrtf(var + 1e-5f);
#pragma unroll 8
    for (int i = 0; i < 32; i++) {
        int c = ln + 32 * i;
        float v = rb[wr * 1024 + c];
        g_n[(size_t)(row0 + wr) * DD + c] = (v - mu) * rstd * nw[c];
    }
}

// ---------------------------------------------------------------------------------
extern "C" void kernel_launch(void* const* d_in, const int* in_sizes, int n_in,
                              void* d_out, int out_size)
{
    const float* x      = (const float*)d_in[0];
    const float* Wq     = (const float*)d_in[1];
    const float* Wk     = (const float*)d_in[2];
    const float* Wv     = (const float*)d_in[3];
    const float* Wgamma = (const float*)d_in[4];
    const float* Wf     = (const float*)d_in[5];
    const float* Wg1    = (const float*)d_in[6];
    const float* Wg2    = (const float*)d_in[7];
    const float* Wo     = (const float*)d_in[8];
    const float* norm_w = (const float*)d_in[9];
    float* out = (float*)d_out;

    float *pq, *pk, *pv, *pn;
    cudaGetSymbolAddress((void**)&pq, g_q);
    cudaGetSymbolAddress((void**)&pk, g_k);
    cudaGetSymbolAddress((void**)&pv, g_v);
    cudaGetSymbolAddress((void**)&pn, g_n);

    dim3 gg(DD / 128, BN / 128);  // (8, 32)
    sgemm_kernel<<<gg, 256>>>(x, Wq, pq, BN, DD, DD, 1);
    sgemm_kernel<<<gg, 256>>>(x, Wk, pk, BN, DD, DD, 1);
    sgemm_kernel<<<gg, 256>>>(x, Wv, pv, BN, DD, DD, 1);
    smallproj_kernel<<<BN / 32, 96>>>(x, Wgamma, Wf, Wg1);
    l2norm_kernel<<<BN * HH / 8, 256>>>();
    recur_kernel<<<128, 64>>>();
    gate_ln_kernel<<<BN / 8, 256>>>(Wg2, norm_w);
    sgemm_kernel<<<gg, 256>>>(pn, Wo, out, BN, DD, DD, 0);
}

// round 2
// speedup vs baseline: 1.0026x; 1.0026x over previous
#include <cuda_runtime.h>
#include <math.h>

#define BB 2
#define NNTOK 2048
#define DD 1024
#define HH 16
#define HDIM 64
#define BN (BB*NNTOK)   /* 4096 rows */

// ---------------- scratch (device globals; no allocation allowed) ----------------
__device__ float g_q [BN*DD];
__device__ float g_k [BN*DD];
__device__ float g_v [BN*DD];
__device__ float g_f [BN*HH];   // f_t   = sigmoid(x @ Wf)      (scalar decay per head)
__device__ float g_g [BN*HH];   // sigmoid(x @ Wgamma)          (gamma = -this)
__device__ float g_g1[BN*HDIM]; // x @ Wg1 (raw)
__device__ float g_o [BN*DD];   // recurrence output
__device__ float g_n [BN*DD];   // gated + layernormed

__device__ __forceinline__ float sigmoidf_(float x) { return 1.f / (1.f + expf(-x)); }

// ---------------- generic fp32 SGEMM: C = act(A[MxK] @ B[KxN]) -------------------
// BM=BN=128, BK=16, 256 threads, 8x8 per thread. M%128==0, N%128==0, K%16==0.
__global__ __launch_bounds__(256) void sgemm_kernel(
    const float* __restrict__ A, const float* __restrict__ B, float* __restrict__ C,
    int M, int N, int K, int act)
{
    __shared__ float As[16][128];
    __shared__ float Bs[16][128];
    const int tid = threadIdx.x;
    const int tx  = tid & 15;
    const int ty  = tid >> 4;
    const int bn  = blockIdx.x;
    const int bm  = blockIdx.y;

    const int arow = tid >> 2;        // 0..63
    const int akc  = (tid & 3) * 4;   // 0,4,8,12
    const int brow = tid >> 5;        // 0..7
    const int bcol = (tid & 31) * 4;  // 0..124

    const float* Ab  = A + (size_t)(bm * 128 + arow) * K + akc;
    const float* Ab2 = Ab + (size_t)64 * K;
    const float* Bb  = B + (size_t)brow * N + bn * 128 + bcol;
    const float* Bb2 = Bb + (size_t)8 * N;

    float acc[8][8];
#pragma unroll
    for (int i = 0; i < 8; i++)
#pragma unroll
        for (int j = 0; j < 8; j++) acc[i][j] = 0.f;

    for (int k0 = 0; k0 < K; k0 += 16) {
        float4 a0 = *(const float4*)(Ab  + k0);
        float4 a1 = *(const float4*)(Ab2 + k0);
        float4 b0 = *(const float4*)(Bb  + (size_t)k0 * N);
        float4 b1 = *(const float4*)(Bb2 + (size_t)k0 * N);
        __syncthreads();
        As[akc + 0][arow] = a0.x; As[akc + 1][arow] = a0.y;
        As[akc + 2][arow] = a0.z; As[akc + 3][arow] = a0.w;
        As[akc + 0][arow + 64] = a1.x; As[akc + 1][arow + 64] = a1.y;
        As[akc + 2][arow + 64] = a1.z; As[akc + 3][arow + 64] = a1.w;
        *(float4*)&Bs[brow    ][bcol] = b0;
        *(float4*)&Bs[brow + 8][bcol] = b1;
        __syncthreads();
#pragma unroll
        for (int kk = 0; kk < 16; kk++) {
            float ar[8], br[8];
            *(float4*)(ar    ) = *(const float4*)&As[kk][ty * 8];
            *(float4*)(ar + 4) = *(const float4*)&As[kk][ty * 8 + 4];
            *(float4*)(br    ) = *(const float4*)&Bs[kk][tx * 8];
            *(float4*)(br + 4) = *(const float4*)&Bs[kk][tx * 8 + 4];
#pragma unroll
            for (int i = 0; i < 8; i++)
#pragma unroll
                for (int j = 0; j < 8; j++)
                    acc[i][j] = fmaf(ar[i], br[j], acc[i][j]);
        }
    }

    const int crow = bm * 128 + ty * 8;
    const int ccol = bn * 128 + tx * 8;
#pragma unroll
    for (int i = 0; i < 8; i++) {
        float v[8];
#pragma unroll
        for (int j = 0; j < 8; j++) {
            float z = acc[i][j];
            v[j] = act ? (z / (1.f + expf(-z))) : z;   // silu
        }
        *(float4*)&C[(size_t)(crow + i) * N + ccol    ] = *(float4*)(v);
        *(float4*)&C[(size_t)(crow + i) * N + ccol + 4] = *(float4*)(v + 4);
    }
}

// ---------- small projections: f = sig(x Wf), g = sig(x Wgamma), g1 = x Wg1 ------
// 32 rows per block, 96 threads (one per output column). Broadcast-LDS inner loop.
__global__ __launch_bounds__(96) void smallproj_kernel(
    const float* __restrict__ x,
    const float* __restrict__ Wgamma, const float* __restrict__ Wf,
    const float* __restrict__ Wg1)
{
    __shared__ float xs[32][64];
    const int row0 = blockIdx.x * 32;
    const int t = threadIdx.x;

    const float* W; int stride, c;
    if (t < 16)      { W = Wgamma; stride = 16; c = t; }
    else if (t < 32) { W = Wf;     stride = 16; c = t - 16; }
    else             { W = Wg1;    stride = 64; c = t - 32; }

    float acc[32];
#pragma unroll
    for (int r = 0; r < 32; r++) acc[r] = 0.f;

    for (int kt = 0; kt < DD; kt += 64) {
        __syncthreads();
        for (int i = t; i < 32 * 64; i += 96) {
            int r = i >> 6, kk = i & 63;
            xs[r][kk] = x[(size_t)(row0 + r) * DD + kt + kk];
        }
        __syncthreads();
#pragma unroll 4
        for (int kk = 0; kk < 64; kk++) {
            float wv = W[(size_t)(kt + kk) * stride + c];
#pragma unroll
            for (int r = 0; r < 32; r++) acc[r] = fmaf(xs[r][kk], wv, acc[r]);
        }
    }

    if (t < 16) {
#pragma unroll
        for (int r = 0; r < 32; r++) g_g[(size_t)(row0 + r) * HH + c] = sigmoidf_(acc[r]);
    } else if (t < 32) {
#pragma unroll
        for (int r = 0; r < 32; r++) g_f[(size_t)(row0 + r) * HH + c] = sigmoidf_(acc[r]);
    } else {
#pragma unroll
        for (int r = 0; r < 32; r++) g_g1[(size_t)(row0 + r) * HDIM + c] = acc[r];
    }
}

// ---------------- l2-normalize k per (b,n,h) over 64 dims ------------------------
__global__ __launch_bounds__(256) void l2norm_kernel()
{
    int hr   = blockIdx.x * 8 + (threadIdx.x >> 5);  // head-row 0..65535
    int lane = threadIdx.x & 31;
    float2* kp = (float2*)(g_k + (size_t)hr * HDIM);
    float2 v = kp[lane];
    float ss = v.x * v.x + v.y * v.y;
#pragma unroll
    for (int o = 16; o; o >>= 1) ss += __shfl_xor_sync(0xffffffffu, ss, o);
    float inv = 1.f / fmaxf(sqrtf(ss), 1e-12f);
    v.x *= inv; v.y *= inv;
    kp[lane] = v;
}

// ---------------- gated delta-rule recurrence ------------------------------------
// grid = 32 (b,h) * 4 colgroups = 128 blocks, 64 threads (2 warps).
// warp handles 8 Dv-columns; lane: col = base + (lane&7), rows (lane>>3)*16..+16.
// Step (f scalar, gamma scalar, k unit-norm):
//   d_j = k . S[:,j] ; u_j = -g f^2 d_j + v_j ; S = f S + k (x) u ; o_j = q . S[:,j]
__global__ __launch_bounds__(64) void recur_kernel()
{
    const int blk = blockIdx.x;
    const int bh  = blk >> 2;
    const int cg  = blk & 3;
    const int b   = bh >> 4;
    const int h   = bh & 15;
    const int w   = threadIdx.x >> 5;
    const int lane = threadIdx.x & 31;
    const int col = cg * 16 + w * 8 + (lane & 7);
    const int r0  = (lane >> 3) * 16;

    const size_t basev = (size_t)b * NNTOK * DD + h * HDIM;
    const float* kp = g_k + basev + r0;
    const float* qp = g_q + basev + r0;
    const float* vp = g_v + basev + col;
    float*       op = g_o + basev + col;
    const float* fp = g_f + (size_t)b * NNTOK * HH + h;
    const float* gp = g_g + (size_t)b * NNTOK * HH + h;

    float S[16];
#pragma unroll
    for (int i = 0; i < 16; i++) S[i] = 0.f;

    float4 kn[4], qn[4]; float vn, fn, gn;
#pragma unroll
    for (int i = 0; i < 4; i++) {
        kn[i] = *(const float4*)(kp + 4 * i);
        qn[i] = *(const float4*)(qp + 4 * i);
    }
    vn = *vp; fn = *fp; gn = *gp;

    for (int t = 0; t < NNTOK; t++) {
        float kc[16], qc[16];
#pragma unroll
        for (int i = 0; i < 4; i++) {
            kc[4*i] = kn[i].x; kc[4*i+1] = kn[i].y; kc[4*i+2] = kn[i].z; kc[4*i+3] = kn[i].w;
            qc[4*i] = qn[i].x; qc[4*i+1] = qn[i].y; qc[4*i+2] = qn[i].z; qc[4*i+3] = qn[i].w;
        }
        const float vc = vn, fc = fn, gc = gn;

        if (t < NNTOK - 1) { kp += DD; qp += DD; vp += DD; fp += HH; gp += HH; }
#pragma unroll
        for (int i = 0; i < 4; i++) {
            kn[i] = *(const float4*)(kp + 4 * i);
            qn[i] = *(const float4*)(qp + 4 * i);
        }
        vn = *vp; fn = *fp; gn = *gp;

        float d0 = 0.f, d1 = 0.f;
#pragma unroll
        for (int i = 0; i < 8; i++)  d0 = fmaf(kc[i], S[i], d0);
#pragma unroll
        for (int i = 8; i < 16; i++) d1 = fmaf(kc[i], S[i], d1);
        float d = d0 + d1;
        d += __shfl_xor_sync(0xffffffffu, d, 8);
        d += __shfl_xor_sync(0xffffffffu, d, 16);

        const float u = fmaf(-gc * fc * fc, d, vc);

        float o0 = 0.f, o1 = 0.f;
#pragma unroll
        for (int i = 0; i < 16; i++) {
            S[i] = fmaf(fc, S[i], kc[i] * u);
            float p = qc[i] * S[i];
            if (i < 8) o0 += p; else o1 += p;
        }
        float o = o0 + o1;
        o += __shfl_xor_sync(0xffffffffu, o, 8);
        o += __shfl_xor_sync(0xffffffffu, o, 16);

        if (lane < 8) op[(size_t)t * DD] = o;
    }
}

// --------- gate = sigmoid(g1 @ Wg2); out = o*gate; LayerNorm(weight) -------------
// 8 rows per block, 256 threads.
__global__ __launch_bounds__(256) void gate_ln_kernel(
    const float* __restrict__ Wg2, const float* __restrict__ nw)
{
    __shared__ float g1s[8 * 64];
    __shared__ float rb[8 * 1024];
    const int row0 = blockIdx.x * 8;
    const int tid = threadIdx.x;

    for (int i = tid; i < 512; i += 256) g1s[i] = g_g1[(size_t)row0 * 64 + i];
    __syncthreads();

#pragma unroll
    for (int cs = 0; cs < 4; cs++) {
        const int c = tid + cs * 256;
        float a[8];
#pragma unroll
        for (int r = 0; r < 8; r++) a[r] = 0.f;
#pragma unroll 4
        for (int k = 0; k < 64; k++) {
            float wv = Wg2[(size_t)k * DD + c];
#pragma unroll
            for (int r = 0; r < 8; r++) a[r] = fmaf(g1s[r * 64 + k], wv, a[r]);
        }
#pragma unroll
        for (int r = 0; r < 8; r++) {
            float gate = 1.f / (1.f + expf(-a[r]));
            rb[r * 1024 + c] = g_o[(size_t)(row0 + r) * DD + c] * gate;
        }
    }
    __syncthreads();

    const int wr = tid >> 5, ln = tid & 31;
    float s = 0.f, s2 = 0.f;
#pragma unroll 8
    for (int i = 0; i < 32; i++) {
        float v = rb[wr * 1024 + ln + 32 * i];
        s += v; s2 = fmaf(v, v, s2);
    }
#pragma unroll
    for (int o = 16; o; o >>= 1) {
        s  += __shfl_xor_sync(0xffffffffu, s,  o);
        s2 += __shfl_xor_sync(0xffffffffu, s2, o);
    }
    const float mu   = s * (1.f / 1024.f);
    const float var  = s2 * (1.f / 1024.f) - mu * mu;
    const float rstd = rsqrtf(var + 1e-5f);
#pragma unroll 8
    for (int i = 0; i < 32; i++) {
        int c = ln + 32 * i;
        float v = rb[wr * 1024 + c];
        g_n[(size_t)(row0 + wr) * DD + c] = (v - mu) * rstd * nw[c];
    }
}

// ---------------------------------------------------------------------------------
extern "C" void kernel_launch(void* const* d_in, const int* in_sizes, int n_in,
                              void* d_out, int out_size)
{
    const float* x      = (const float*)d_in[0];
    const float* Wq     = (const float*)d_in[1];
    const float* Wk     = (const float*)d_in[2];
    const float* Wv     = (const float*)d_in[3];
    const float* Wgamma = (const float*)d_in[4];
    const float* Wf     = (const float*)d_in[5];
    const float* Wg1    = (const float*)d_in[6];
    const float* Wg2    = (const float*)d_in[7];
    const float* Wo     = (const float*)d_in[8];
    const float* norm_w = (const float*)d_in[9];
    float* out = (float*)d_out;

    float *pq, *pk, *pv, *pn;
    cudaGetSymbolAddress((void**)&pq, g_q);
    cudaGetSymbolAddress((void**)&pk, g_k);
    cudaGetSymbolAddress((void**)&pv, g_v);
    cudaGetSymbolAddress((void**)&pn, g_n);

    dim3 gg(DD / 128, BN / 128);  // (8, 32)
    sgemm_kernel<<<gg, 256>>>(x, Wq, pq, BN, DD, DD, 1);
    sgemm_kernel<<<gg, 256>>>(x, Wk, pk, BN, DD, DD, 1);
    sgemm_kernel<<<gg, 256>>>(x, Wv, pv, BN, DD, DD, 1);
    smallproj_kernel<<<BN / 32, 96>>>(x, Wgamma, Wf, Wg1);
    l2norm_kernel<<<BN * HH / 8, 256>>>();
    recur_kernel<<<128, 64>>>();
    gate_ln_kernel<<<BN / 8, 256>>>(Wg2, norm_w);
    sgemm_kernel<<<gg, 256>>>(pn, Wo, out, BN, DD, DD, 0);
}

// round 4
// speedup vs baseline: 1.3157x; 1.3123x over previous
#include <cuda_runtime.h>
#include <cuda_bf16.h>
#include <math.h>
#include <stdint.h>

#define BB 2
#define NNTOK 2048
#define DD 1024
#define HH 16
#define HDIM 64
#define BN (BB*NNTOK)

// ---------------- scratch (device globals) ----------------------------------
__device__ __nv_bfloat16 g_xhi[BN*DD], g_xlo[BN*DD];
__device__ __nv_bfloat16 g_nhi[BN*DD], g_nlo[BN*DD];
__device__ __nv_bfloat16 g_wqhi[DD*DD], g_wqlo[DD*DD];
__device__ __nv_bfloat16 g_wkhi[DD*DD], g_wklo[DD*DD];
__device__ __nv_bfloat16 g_wvhi[DD*DD], g_wvlo[DD*DD];
__device__ __nv_bfloat16 g_wohi[DD*DD], g_wolo[DD*DD];
__device__ __nv_bfloat16 g_wshi[128*DD], g_wslo[128*DD];
__device__ float g_q [BN*DD];
__device__ float g_k [BN*DD];
__device__ float g_v [BN*DD];
__device__ float g_o [BN*DD];
__device__ float g_n [BN*DD];
__device__ float g_f [BN*HH];
__device__ float g_g [BN*HH];
__device__ float g_g1[BN*HDIM];

__device__ __forceinline__ float sigmoidf_(float x) { return 1.f / (1.f + expf(-x)); }

__device__ __forceinline__ uint32_t s2u(const void* p) {
    uint32_t a;
    asm("{ .reg .u64 t; cvta.to.shared.u64 t, %1; cvt.u32.u64 %0, t; }" : "=r"(a) : "l"(p));
    return a;
}
__device__ __forceinline__ void cp16(uint32_t dst, const void* src) {
    asm volatile("cp.async.cg.shared.global [%0], [%1], 16;" :: "r"(dst), "l"(src) : "memory");
}
__device__ __forceinline__ void mma16816(float* d, const uint32_t* a, const uint32_t* b) {
    asm volatile("mma.sync.aligned.m16n8k16.row.col.f32.bf16.bf16.f32 "
        "{%0,%1,%2,%3}, {%4,%5,%6,%7}, {%8,%9}, {%0,%1,%2,%3};"
        : "+f"(d[0]), "+f"(d[1]), "+f"(d[2]), "+f"(d[3])
        : "r"(a[0]), "r"(a[1]), "r"(a[2]), "r"(a[3]), "r"(b[0]), "r"(b[1]));
}

// ---------------- conversions ------------------------------------------------
// fp32 [M x 1024] row-major -> hi/lo bf16 arrays
__global__ __launch_bounds__(256) void conv_a(const float* __restrict__ src,
                                              __nv_bfloat16* __restrict__ hi,
                                              __nv_bfloat16* __restrict__ lo) {
    int i = blockIdx.x * 256 + threadIdx.x;
    float v = src[i];
    __nv_bfloat16 h = __float2bfloat16(v);
    hi[i] = h;
    lo[i] = __float2bfloat16(v - __bfloat162float(h));
}

// W[1024][1024] -> Wt[n][k] hi/lo (transpose)
__global__ __launch_bounds__(256) void conv_wT(const float* __restrict__ W,
                                               __nv_bfloat16* __restrict__ hi,
                                               __nv_bfloat16* __restrict__ lo) {
    __shared__ float ts[32][33];
    const int bx = blockIdx.x, by = blockIdx.y;
    const int r = threadIdx.x >> 5, c = threadIdx.x & 31;
#pragma unroll
    for (int i = 0; i < 4; i++)
        ts[r + 8*i][c] = W[(size_t)(by*32 + r + 8*i) * DD + bx*32 + c];
    __syncthreads();
#pragma unroll
    for (int i = 0; i < 4; i++) {
        int n = bx*32 + r + 8*i, k = by*32 + c;
        float v = ts[c][r + 8*i];
        __nv_bfloat16 h = __float2bfloat16(v);
        hi[(size_t)n*DD + k] = h;
        lo[(size_t)n*DD + k] = __float2bfloat16(v - __bfloat162float(h));
    }
}

// combined small weights -> ws[n][k]: n 0-15 Wgamma, 16-31 Wf, 32-95 Wg1, 96-127 zero
__global__ __launch_bounds__(256) void conv_small(const float* __restrict__ Wg,
                                                  const float* __restrict__ Wf,
                                                  const float* __restrict__ Wg1) {
    int n = blockIdx.x;
    for (int k = threadIdx.x; k < DD; k += 256) {
        float v = (n < 16) ? Wg[(size_t)k*16 + n] : (n < 32) ? Wf[(size_t)k*16 + n - 16]
                : (n < 96) ? Wg1[(size_t)k*64 + n - 32] : 0.f;
        __nv_bfloat16 h = __float2bfloat16(v);
        g_wshi[(size_t)n*DD + k] = h;
        g_wslo[(size_t)n*DD + k] = __float2bfloat16(v - __bfloat162float(h));
    }
}

// ---------------- bf16 split GEMM via mma.sync --------------------------------
// C[tile 128x128] = sum over K'=3072: A(seg: hi,lo,hi) . B(seg: hi,hi,lo)^T
// 256 threads, 8 warps (2m x 4n), warp tile 64x32. Double-buffered cp.async.
// mode: 0 plain store, 1 silu store, 3 small scatter
#define PITCH 80
#define ABUF (128*PITCH)            /* 10240 */
#define BUFSZ (2*ABUF)              /* 20480 */
__global__ __launch_bounds__(256) void gemm_mma(
    const __nv_bfloat16* __restrict__ Ahi, const __nv_bfloat16* __restrict__ Alo,
    const __nv_bfloat16* __restrict__ Bhi, const __nv_bfloat16* __restrict__ Blo,
    float* __restrict__ C, int mode)
{
    __shared__ __align__(16) char sm[2 * BUFSZ];
    const uint32_t sb = s2u(sm);
    const int tid = threadIdx.x, wid = tid >> 5, lane = tid & 31;
    const int wm = wid >> 2, wn = wid & 3;          // 2 x 4 warps
    const int m0 = blockIdx.y * 128, n0 = blockIdx.x * 128;

    float acc[4][4][4];
#pragma unroll
    for (int i = 0; i < 4; i++)
#pragma unroll
        for (int j = 0; j < 4; j++)
#pragma unroll
            for (int l = 0; l < 4; l++) acc[i][j][l] = 0.f;

    auto load_chunk = [&](int kf, int buf) {
        const int seg = kf >> 5;
        const __nv_bfloat16* Aa = (seg == 1) ? Alo : Ahi;
        const __nv_bfloat16* Ba = (seg == 2) ? Blo : Bhi;
        const int kl = (kf & 31) * 32;
        const uint32_t base = sb + buf * BUFSZ;
#pragma unroll
        for (int i = 0; i < 2; i++) {
            int idx = tid + i * 256;                 // 0..511
            int row = idx >> 2, q = idx & 3;
            cp16(base + row * PITCH + q * 16,
                 Aa + (size_t)(m0 + row) * DD + kl + q * 8);
            cp16(base + ABUF + row * PITCH + q * 16,
                 Ba + (size_t)(n0 + row) * DD + kl + q * 8);
        }
        asm volatile("cp.async.commit_group;" ::: "memory");
    };

    load_chunk(0, 0);

    for (int kc = 0; kc < 96; kc++) {
        const int buf = kc & 1;
        if (kc + 1 < 96) {
            load_chunk(kc + 1, buf ^ 1);
            asm volatile("cp.async.wait_group 1;" ::: "memory");
        } else {
            asm volatile("cp.async.wait_group 0;" ::: "memory");
        }
        __syncthreads();

        const uint32_t As = sb + buf * BUFSZ;
        const uint32_t Bs = As + ABUF;
        const int ar = lane >> 2, kb = (lane & 3) * 4;
#pragma unroll
        for (int ks = 0; ks < 2; ks++) {
            uint32_t a[4][4], b[4][2];
#pragma unroll
            for (int mi = 0; mi < 4; mi++) {
                uint32_t ra = As + (wm*64 + mi*16 + ar) * PITCH + ks*32 + kb;
                asm volatile("ld.shared.b32 %0, [%1];"      : "=r"(a[mi][0]) : "r"(ra));
                asm volatile("ld.shared.b32 %0, [%1];"      : "=r"(a[mi][1]) : "r"(ra + 8*PITCH));
                asm volatile("ld.shared.b32 %0, [%1];"      : "=r"(a[mi][2]) : "r"(ra + 16));
                asm volatile("ld.shared.b32 %0, [%1];"      : "=r"(a[mi][3]) : "r"(ra + 8*PITCH + 16));
            }
#pragma unroll
            for (int ni = 0; ni < 4; ni++) {
                uint32_t rb = Bs + (wn*32 + ni*8 + ar) * PITCH + ks*32 + kb;
                asm volatile("ld.shared.b32 %0, [%1];" : "=r"(b[ni][0]) : "r"(rb));
                asm volatile("ld.shared.b32 %0, [%1];" : "=r"(b[ni][1]) : "r"(rb + 16));
            }
#pragma unroll
            for (int mi = 0; mi < 4; mi++)
#pragma unroll
                for (int ni = 0; ni < 4; ni++)
                    mma16816(acc[mi][ni], a[mi], b[ni]);
        }
        __syncthreads();
    }

    // epilogue
    const int r_lo = lane >> 2, c_lo = (lane & 3) * 2;
#pragma unroll
    for (int mi = 0; mi < 4; mi++) {
#pragma unroll
        for (int ni = 0; ni < 4; ni++) {
#pragma unroll
            for (int half = 0; half < 2; half++) {
                int row = m0 + wm*64 + mi*16 + r_lo + half*8;
                int col = n0 + wn*32 + ni*8 + c_lo;
                float v0 = acc[mi][ni][half*2], v1 = acc[mi][ni][half*2 + 1];
                if (mode == 1) { v0 *= sigmoidf_(v0); v1 *= sigmoidf_(v1); }
                if (mode == 3) {
#pragma unroll
                    for (int e = 0; e < 2; e++) {
                        int cc = col + e;
                        float z = e ? v1 : v0;
                        if (cc < 16)      g_g [(size_t)row*HH + cc]        = sigmoidf_(z);
                        else if (cc < 32) g_f [(size_t)row*HH + cc - 16]   = sigmoidf_(z);
                        else if (cc < 96) g_g1[(size_t)row*HDIM + cc - 32] = z;
                    }
                } else {
                    *(float2*)(C + (size_t)row * DD + col) = make_float2(v0, v1);
                }
            }
        }
    }
}

// ---------------- l2-normalize k per head-row over 64 dims -------------------
__global__ __launch_bounds__(256) void l2norm_kernel() {
    int hr = blockIdx.x * 8 + (threadIdx.x >> 5);
    int lane = threadIdx.x & 31;
    float2* kp = (float2*)(g_k + (size_t)hr * HDIM);
    float2 v = kp[lane];
    float ss = v.x * v.x + v.y * v.y;
#pragma unroll
    for (int o = 16; o; o >>= 1) ss += __shfl_xor_sync(0xffffffffu, ss, o);
    float inv = 1.f / fmaxf(sqrtf(ss), 1e-12f);
    v.x *= inv; v.y *= inv;
    kp[lane] = v;
}

// ---------------- gated delta-rule recurrence --------------------------------
__global__ __launch_bounds__(64) void recur_kernel() {
    const int blk = blockIdx.x;
    const int bh = blk >> 2, cg = blk & 3;
    const int b = bh >> 4, h = bh & 15;
    const int w = threadIdx.x >> 5, lane = threadIdx.x & 31;
    const int col = cg * 16 + w * 8 + (lane & 7);
    const int r0 = (lane >> 3) * 16;

    const size_t basev = (size_t)b * NNTOK * DD + h * HDIM;
    const float* kp = g_k + basev + r0;
    const float* qp = g_q + basev + r0;
    const float* vp = g_v + basev + col;
    float*       op = g_o + basev + col;
    const float* fp = g_f + (size_t)b * NNTOK * HH + h;
    const float* gp = g_g + (size_t)b * NNTOK * HH + h;

    float S[16];
#pragma unroll
    for (int i = 0; i < 16; i++) S[i] = 0.f;

    float4 kn[4], qn[4]; float vn, fn, gn;
#pragma unroll
    for (int i = 0; i < 4; i++) { kn[i] = *(const float4*)(kp + 4*i); qn[i] = *(const float4*)(qp + 4*i); }
    vn = *vp; fn = *fp; gn = *gp;

    for (int t = 0; t < NNTOK; t++) {
        float kc[16], qc[16];
#pragma unroll
        for (int i = 0; i < 4; i++) {
            kc[4*i] = kn[i].x; kc[4*i+1] = kn[i].y; kc[4*i+2] = kn[i].z; kc[4*i+3] = kn[i].w;
            qc[4*i] = qn[i].x; qc[4*i+1] = qn[i].y; qc[4*i+2] = qn[i].z; qc[4*i+3] = qn[i].w;
        }
        const float vc = vn, fc = fn, gc = gn;
        if (t < NNTOK - 1) { kp += DD; qp += DD; vp += DD; fp += HH; gp += HH; }
#pragma unroll
        for (int i = 0; i < 4; i++) { kn[i] = *(const float4*)(kp + 4*i); qn[i] = *(const float4*)(qp + 4*i); }
        vn = *vp; fn = *fp; gn = *gp;

        float d0 = 0.f, d1 = 0.f;
#pragma unroll
        for (int i = 0; i < 8; i++)  d0 = fmaf(kc[i], S[i], d0);
#pragma unroll
        for (int i = 8; i < 16; i++) d1 = fmaf(kc[i], S[i], d1);
        float d = d0 + d1;
        d += __shfl_xor_sync(0xffffffffu, d, 8);
        d += __shfl_xor_sync(0xffffffffu, d, 16);

        const float u = fmaf(-gc * fc * fc, d, vc);
        float o0 = 0.f, o1 = 0.f;
#pragma unroll
        for (int i = 0; i < 16; i++) {
            S[i] = fmaf(fc, S[i], kc[i] * u);
            float p = qc[i] * S[i];
            if (i < 8) o0 += p; else o1 += p;
        }
        float o = o0 + o1;
        o += __shfl_xor_sync(0xffffffffu, o, 8);
        o += __shfl_xor_sync(0xffffffffu, o, 16);
        if (lane < 8) op[(size_t)t * DD] = o;
    }
}

// -------- gate + LayerNorm -> g_n --------------------------------------------
__global__ __launch_bounds__(256) void gate_ln_kernel(const float* __restrict__ Wg2,
                                                      const float* __restrict__ nw) {
    __shared__ float g1s[8 * 64];
    __shared__ float rb[8 * 1024];
    const int row0 = blockIdx.x * 8;
    const int tid = threadIdx.x;
    for (int i = tid; i < 512; i += 256) g1s[i] = g_g1[(size_t)row0 * 64 + i];
    __syncthreads();
#pragma unroll
    for (int cs = 0; cs < 4; cs++) {
        const int c = tid + cs * 256;
        float a[8];
#pragma unroll
        for (int r = 0; r < 8; r++) a[r] = 0.f;
#pragma unroll 4
        for (int k = 0; k < 64; k++) {
            float wv = Wg2[(size_t)k * DD + c];
#pragma unroll
            for (int r = 0; r < 8; r++) a[r] = fmaf(g1s[r * 64 + k], wv, a[r]);
        }
#pragma unroll
        for (int r = 0; r < 8; r++)
            rb[r * 1024 + c] = g_o[(size_t)(row0 + r) * DD + c] * sigmoidf_(a[r]);
    }
    __syncthreads();
    const int wr = tid >> 5, ln = tid & 31;
    float s = 0.f, s2 = 0.f;
#pragma unroll 8
    for (int i = 0; i < 32; i++) {
        float v = rb[wr * 1024 + ln + 32 * i];
        s += v; s2 = fmaf(v, v, s2);
    }
#pragma unroll
    for (int o = 16; o; o >>= 1) {
        s  += __shfl_xor_sync(0xffffffffu, s,  o);
        s2 += __shfl_xor_sync(0xffffffffu, s2, o);
    }
    const float mu = s * (1.f / 1024.f);
    const float rstd = rsqrtf(s2 * (1.f / 1024.f) - mu * mu + 1e-5f);
#pragma unroll 8
    for (int i = 0; i < 32; i++) {
        int c = ln + 32 * i;
        g_n[(size_t)(row0 + wr) * DD + c] = (rb[wr * 1024 + c] - mu) * rstd * nw[c];
    }
}

// -----------------------------------------------------------------------------
extern "C" void kernel_launch(void* const* d_in, const int* in_sizes, int n_in,
                              void* d_out, int out_size) {
    const float* x      = (const float*)d_in[0];
    const float* Wq     = (const float*)d_in[1];
    const float* Wk     = (const float*)d_in[2];
    const float* Wv     = (const float*)d_in[3];
    const float* Wgamma = (const float*)d_in[4];
    const float* Wf     = (const float*)d_in[5];
    const float* Wg1    = (const float*)d_in[6];
    const float* Wg2    = (const float*)d_in[7];
    const float* Wo     = (const float*)d_in[8];
    const float* norm_w = (const float*)d_in[9];
    float* out = (float*)d_out;

    __nv_bfloat16 *xh, *xl, *nh, *nl, *qh, *ql, *kh, *kl_, *vh, *vl, *oh, *ol, *sh, *sl;
    float *pq, *pk, *pv, *pn;
    cudaGetSymbolAddress((void**)&xh, g_xhi);  cudaGetSymbolAddress((void**)&xl, g_xlo);
    cudaGetSymbolAddress((void**)&nh, g_nhi);  cudaGetSymbolAddress((void**)&nl, g_nlo);
    cudaGetSymbolAddress((void**)&qh, g_wqhi); cudaGetSymbolAddress((void**)&ql, g_wqlo);
    cudaGetSymbolAddress((void**)&kh, g_wkhi); cudaGetSymbolAddress((void**)&kl_, g_wklo);
    cudaGetSymbolAddress((void**)&vh, g_wvhi); cudaGetSymbolAddress((void**)&vl, g_wvlo);
    cudaGetSymbolAddress((void**)&oh, g_wohi); cudaGetSymbolAddress((void**)&ol, g_wolo);
    cudaGetSymbolAddress((void**)&sh, g_wshi); cudaGetSymbolAddress((void**)&sl, g_wslo);
    cudaGetSymbolAddress((void**)&pq, g_q);    cudaGetSymbolAddress((void**)&pk, g_k);
    cudaGetSymbolAddress((void**)&pv, g_v);    cudaGetSymbolAddress((void**)&pn, g_n);

    dim3 wt(32, 32);
    conv_a<<<BN*DD/256, 256>>>(x, xh, xl);
    conv_wT<<<wt, 256>>>(Wq, qh, ql);
    conv_wT<<<wt, 256>>>(Wk, kh, kl_);
    conv_wT<<<wt, 256>>>(Wv, vh, vl);
    conv_wT<<<wt, 256>>>(Wo, oh, ol);
    conv_small<<<128, 256>>>(Wgamma, Wf, Wg1);

    dim3 gg(8, 32);
    gemm_mma<<<gg, 256>>>(xh, xl, qh, ql, pq, 1);
    gemm_mma<<<gg, 256>>>(xh, xl, kh, kl_, pk, 1);
    gemm_mma<<<gg, 256>>>(xh, xl, vh, vl, pv, 1);
    gemm_mma<<<dim3(1, 32), 256>>>(xh, xl, sh, sl, pq /*unused*/, 3);

    l2norm_kernel<<<BN*HH/8, 256>>>();
    recur_kernel<<<128, 64>>>();
    gate_ln_kernel<<<BN/8, 256>>>(Wg2, norm_w);
    conv_a<<<BN*DD/256, 256>>>(pn, nh, nl);
    gemm_mma<<<gg, 256>>>(nh, nl, oh, ol, out, 0);
}

// round 5
// speedup vs baseline: 1.6729x; 1.2714x over previous
#include <cuda_runtime.h>
#include <cuda_bf16.h>
#include <math.h>
#include <stdint.h>

#define BB 2
#define NNTOK 2048
#define DD 1024
#define HH 16
#define HDIM 64
#define BN (BB*NNTOK)

// ---------------- scratch (device globals) ----------------------------------
__device__ __nv_bfloat16 g_xhi[BN*DD], g_xlo[BN*DD];
__device__ __nv_bfloat16 g_nhi[BN*DD], g_nlo[BN*DD];
__device__ __nv_bfloat16 g_wqhi[DD*DD], g_wqlo[DD*DD];
__device__ __nv_bfloat16 g_wkhi[DD*DD], g_wklo[DD*DD];
__device__ __nv_bfloat16 g_wvhi[DD*DD], g_wvlo[DD*DD];
__device__ __nv_bfloat16 g_wohi[DD*DD], g_wolo[DD*DD];
__device__ __nv_bfloat16 g_wshi[128*DD], g_wslo[128*DD];
__device__ float g_q [BN*DD];
__device__ float g_k [BN*DD];
__device__ float g_v [BN*DD];
__device__ float g_o [BN*DD];
__device__ float g_n [BN*DD];
__device__ float g_f [BN*HH];
__device__ float g_g [BN*HH];
__device__ float g_g1[BN*HDIM];

__device__ __forceinline__ float sigmoidf_(float x) { return 1.f / (1.f + expf(-x)); }

__device__ __forceinline__ uint32_t s2u(const void* p) {
    uint32_t a;
    asm("{ .reg .u64 t; cvta.to.shared.u64 t, %1; cvt.u32.u64 %0, t; }" : "=r"(a) : "l"(p));
    return a;
}
__device__ __forceinline__ void cp16(uint32_t dst, const void* src) {
    asm volatile("cp.async.cg.shared.global [%0], [%1], 16;" :: "r"(dst), "l"(src) : "memory");
}
__device__ __forceinline__ void ldm4(uint32_t* r, uint32_t addr) {
    asm volatile("ldmatrix.sync.aligned.m8n8.x4.shared.b16 {%0,%1,%2,%3}, [%4];"
        : "=r"(r[0]), "=r"(r[1]), "=r"(r[2]), "=r"(r[3]) : "r"(addr));
}
__device__ __forceinline__ void mma16816(float* d, const uint32_t* a, const uint32_t* b) {
    asm volatile("mma.sync.aligned.m16n8k16.row.col.f32.bf16.bf16.f32 "
        "{%0,%1,%2,%3}, {%4,%5,%6,%7}, {%8,%9}, {%0,%1,%2,%3};"
        : "+f"(d[0]), "+f"(d[1]), "+f"(d[2]), "+f"(d[3])
        : "r"(a[0]), "r"(a[1]), "r"(a[2]), "r"(a[3]), "r"(b[0]), "r"(b[1]));
}

// ---------------- conversions ------------------------------------------------
__global__ __launch_bounds__(256) void conv_a(const float* __restrict__ src,
                                              __nv_bfloat16* __restrict__ hi,
                                              __nv_bfloat16* __restrict__ lo) {
    int i = blockIdx.x * 256 + threadIdx.x;
    float v = src[i];
    __nv_bfloat16 h = __float2bfloat16(v);
    hi[i] = h;
    lo[i] = __float2bfloat16(v - __bfloat162float(h));
}

// 4 weight transposes in one launch: blockIdx.z selects the weight
__global__ __launch_bounds__(256) void conv_wT4(
    const float* __restrict__ W0, const float* __restrict__ W1,
    const float* __restrict__ W2, const float* __restrict__ W3,
    __nv_bfloat16* __restrict__ h0, __nv_bfloat16* __restrict__ l0,
    __nv_bfloat16* __restrict__ h1, __nv_bfloat16* __restrict__ l1,
    __nv_bfloat16* __restrict__ h2, __nv_bfloat16* __restrict__ l2,
    __nv_bfloat16* __restrict__ h3, __nv_bfloat16* __restrict__ l3)
{
    const float* W; __nv_bfloat16 *hi, *lo;
    switch (blockIdx.z) {
        case 0: W = W0; hi = h0; lo = l0; break;
        case 1: W = W1; hi = h1; lo = l1; break;
        case 2: W = W2; hi = h2; lo = l2; break;
        default: W = W3; hi = h3; lo = l3; break;
    }
    __shared__ float ts[32][33];
    const int bx = blockIdx.x, by = blockIdx.y;
    const int r = threadIdx.x >> 5, c = threadIdx.x & 31;
#pragma unroll
    for (int i = 0; i < 4; i++)
        ts[r + 8*i][c] = W[(size_t)(by*32 + r + 8*i) * DD + bx*32 + c];
    __syncthreads();
#pragma unroll
    for (int i = 0; i < 4; i++) {
        int n = bx*32 + r + 8*i, k = by*32 + c;
        float v = ts[c][r + 8*i];
        __nv_bfloat16 h = __float2bfloat16(v);
        hi[(size_t)n*DD + k] = h;
        lo[(size_t)n*DD + k] = __float2bfloat16(v - __bfloat162float(h));
    }
}

__global__ __launch_bounds__(256) void conv_small(const float* __restrict__ Wg,
                                                  const float* __restrict__ Wf,
                                                  const float* __restrict__ Wg1) {
    int n = blockIdx.x;
    for (int k = threadIdx.x; k < DD; k += 256) {
        float v = (n < 16) ? Wg[(size_t)k*16 + n] : (n < 32) ? Wf[(size_t)k*16 + n - 16]
                : (n < 96) ? Wg1[(size_t)k*64 + n - 32] : 0.f;
        __nv_bfloat16 h = __float2bfloat16(v);
        g_wshi[(size_t)n*DD + k] = h;
        g_wslo[(size_t)n*DD + k] = __float2bfloat16(v - __bfloat162float(h));
    }
}

// ---------------- bf16 split GEMM via mma.sync + ldmatrix --------------------
// C[128x128 tile] = sum over K'=3072 of A(seg hi,lo,hi) . B(seg hi,hi,lo)^T
// 8 warps (2m x 4n), warp tile 64x32. 4-stage cp.async ring, 1 sync/chunk.
#define PITCH 80
#define ABUF (128*PITCH)
#define STG (2*ABUF)
#define NSTG 4
#define GSMEM (NSTG*STG)   /* 81920 */
__global__ __launch_bounds__(256) void gemm_mma(
    const __nv_bfloat16* __restrict__ Ahi, const __nv_bfloat16* __restrict__ Alo,
    const __nv_bfloat16* __restrict__ Bhi, const __nv_bfloat16* __restrict__ Blo,
    float* __restrict__ C, int mode)
{
    extern __shared__ __align__(16) char sm[];
    const uint32_t sb = s2u(sm);
    const int tid = threadIdx.x, wid = tid >> 5, lane = tid & 31;
    const int wm = wid >> 2, wn = wid & 3;
    const int m0 = blockIdx.y * 128, n0 = blockIdx.x * 128;

    float acc[4][4][4];
#pragma unroll
    for (int i = 0; i < 4; i++)
#pragma unroll
        for (int j = 0; j < 4; j++)
#pragma unroll
            for (int l = 0; l < 4; l++) acc[i][j][l] = 0.f;

    auto load_chunk = [&](int kf) {
        const int seg = kf >> 5;
        const __nv_bfloat16* Aa = (seg == 1) ? Alo : Ahi;
        const __nv_bfloat16* Ba = (seg == 2) ? Blo : Bhi;
        const int kl = (kf & 31) * 32;
        const uint32_t base = sb + (uint32_t)(kf & 3) * STG;
#pragma unroll
        for (int i = 0; i < 2; i++) {
            int idx = tid + i * 256;
            int row = idx >> 2, q = idx & 3;
            cp16(base + row * PITCH + q * 16, Aa + (size_t)(m0 + row) * DD + kl + q * 8);
            cp16(base + ABUF + row * PITCH + q * 16, Ba + (size_t)(n0 + row) * DD + kl + q * 8);
        }
        asm volatile("cp.async.commit_group;" ::: "memory");
    };

    load_chunk(0); load_chunk(1); load_chunk(2);

    const int la = lane & 15, lb8 = (lane >> 4) * 16;          // A ldmatrix addr parts
    const int rb_row = ((lane >> 4) & 1) * 8 + (lane & 7);     // B ldmatrix row part
    const int rb_col = ((lane >> 3) & 1) * 16;                 // B ldmatrix col byte

    for (int kc = 0; kc < 96; kc++) {
        asm volatile("cp.async.wait_group 2;" ::: "memory");
        __syncthreads();
        if (kc + 3 < 96) load_chunk(kc + 3);
        else asm volatile("cp.async.commit_group;" ::: "memory");

        const uint32_t As = sb + (uint32_t)(kc & 3) * STG;
        const uint32_t Bs = As + ABUF;
#pragma unroll
        for (int ks = 0; ks < 2; ks++) {
            uint32_t a[4][4], b[4][2];
#pragma unroll
            for (int mi = 0; mi < 4; mi++)
                ldm4(a[mi], As + (uint32_t)((wm*64 + mi*16 + la) * PITCH + ks*32 + lb8));
#pragma unroll
            for (int nj = 0; nj < 2; nj++) {
                uint32_t t[4];
                ldm4(t, Bs + (uint32_t)((wn*32 + nj*16 + rb_row) * PITCH + ks*32 + rb_col));
                b[nj*2][0] = t[0]; b[nj*2][1] = t[1];
                b[nj*2+1][0] = t[2]; b[nj*2+1][1] = t[3];
            }
#pragma unroll
            for (int mi = 0; mi < 4; mi++)
#pragma unroll
                for (int ni = 0; ni < 4; ni++)
                    mma16816(acc[mi][ni], a[mi], b[ni]);
        }
    }

    const int r_lo = lane >> 2, c_lo = (lane & 3) * 2;
#pragma unroll
    for (int mi = 0; mi < 4; mi++) {
#pragma unroll
        for (int ni = 0; ni < 4; ni++) {
#pragma unroll
            for (int half = 0; half < 2; half++) {
                int row = m0 + wm*64 + mi*16 + r_lo + half*8;
                int col = n0 + wn*32 + ni*8 + c_lo;
                float v0 = acc[mi][ni][half*2], v1 = acc[mi][ni][half*2 + 1];
                if (mode == 1) { v0 *= sigmoidf_(v0); v1 *= sigmoidf_(v1); }
                if (mode == 3) {
#pragma unroll
                    for (int e = 0; e < 2; e++) {
                        int cc = col + e;
                        float z = e ? v1 : v0;
                        if (cc < 16)      g_g [(size_t)row*HH + cc]        = sigmoidf_(z);
                        else if (cc < 32) g_f [(size_t)row*HH + cc - 16]   = sigmoidf_(z);
                        else if (cc < 96) g_g1[(size_t)row*HDIM + cc - 32] = z;
                    }
                } else {
                    *(float2*)(C + (size_t)row * DD + col) = make_float2(v0, v1);
                }
            }
        }
    }
}

// ---------------- l2-normalize k per head-row over 64 dims -------------------
__global__ __launch_bounds__(256) void l2norm_kernel() {
    int hr = blockIdx.x * 8 + (threadIdx.x >> 5);
    int lane = threadIdx.x & 31;
    float2* kp = (float2*)(g_k + (size_t)hr * HDIM);
    float2 v = kp[lane];
    float ss = v.x * v.x + v.y * v.y;
#pragma unroll
    for (int o = 16; o; o >>= 1) ss += __shfl_xor_sync(0xffffffffu, ss, o);
    float inv = 1.f / fmaxf(sqrtf(ss), 1e-12f);
    v.x *= inv; v.y *= inv;
    kp[lane] = v;
}

// ---------------- gated delta-rule recurrence (3-slot, depth-2 prefetch) -----
__global__ __launch_bounds__(64) void recur_kernel() {
    const int blk = blockIdx.x;
    const int bh = blk >> 2, cg = blk & 3;
    const int b = bh >> 4, h = bh & 15;
    const int w = threadIdx.x >> 5, lane = threadIdx.x & 31;
    const int col = cg * 16 + w * 8 + (lane & 7);
    const int r0 = (lane >> 3) * 16;

    const size_t basev = (size_t)b * NNTOK * DD + h * HDIM;
    const float* kp = g_k + basev + r0;
    const float* qp = g_q + basev + r0;
    const float* vp = g_v + basev + col;
    float*       op = g_o + basev + col;
    const float* fp = g_f + (size_t)b * NNTOK * HH + h;
    const float* gp = g_g + (size_t)b * NNTOK * HH + h;

    float S[16];
#pragma unroll
    for (int i = 0; i < 16; i++) S[i] = 0.f;

    float4 kb[3][4], qb[3][4]; float vb[3], fb[3], gb[3];
    int tl = 0;  // index of next load
    auto prefetch = [&](int slot) {
#pragma unroll
        for (int i = 0; i < 4; i++) { kb[slot][i] = *(const float4*)(kp + 4*i); qb[slot][i] = *(const float4*)(qp + 4*i); }
        vb[slot] = *vp; fb[slot] = *fp; gb[slot] = *gp;
        if (tl < NNTOK - 1) { kp += DD; qp += DD; vp += DD; fp += HH; gp += HH; }
        tl++;
    };
    prefetch(0); prefetch(1);

    int t = 0;
    for (int it = 0; it < 683; it++) {
#pragma unroll
        for (int j = 0; j < 3; j++) {
            prefetch((j + 2) % 3);   // load t+2 into the slot freed at step t-1

            const float4* kf4 = kb[j];
            const float4* qf4 = qb[j];
            float kc[16], qc[16];
#pragma unroll
            for (int i = 0; i < 4; i++) {
                kc[4*i] = kf4[i].x; kc[4*i+1] = kf4[i].y; kc[4*i+2] = kf4[i].z; kc[4*i+3] = kf4[i].w;
                qc[4*i] = qf4[i].x; qc[4*i+1] = qf4[i].y; qc[4*i+2] = qf4[i].z; qc[4*i+3] = qf4[i].w;
            }
            const float vc = vb[j], fc = fb[j], gc = gb[j];

            float p0 = 0.f, p1 = 0.f, p2 = 0.f, p3 = 0.f;
#pragma unroll
            for (int i = 0; i < 4; i++) {
                p0 = fmaf(kc[i],    S[i],    p0);
                p1 = fmaf(kc[i+4],  S[i+4],  p1);
                p2 = fmaf(kc[i+8],  S[i+8],  p2);
                p3 = fmaf(kc[i+12], S[i+12], p3);
            }
            float d = (p0 + p1) + (p2 + p3);
            d += __shfl_xor_sync(0xffffffffu, d, 8);
            d += __shfl_xor_sync(0xffffffffu, d, 16);

            const float u = fmaf(-gc * fc * fc, d, vc);
            float o0 = 0.f, o1 = 0.f;
#pragma unroll
            for (int i = 0; i < 16; i++) {
                S[i] = fmaf(fc, S[i], kc[i] * u);
                float p = qc[i] * S[i];
                if (i < 8) o0 += p; else o1 += p;
            }
            float o = o0 + o1;
            o += __shfl_xor_sync(0xffffffffu, o, 8);
            o += __shfl_xor_sync(0xffffffffu, o, 16);
            if (lane < 8 && t < NNTOK) op[(size_t)t * DD] = o;
            t++;
        }
    }
}

// -------- gate + LayerNorm -> g_n --------------------------------------------
__global__ __launch_bounds__(256) void gate_ln_kernel(const float* __restrict__ Wg2,
                                                      const float* __restrict__ nw) {
    __shared__ float g1s[8 * 64];
    __shared__ float rb[8 * 1024];
    const int row0 = blockIdx.x * 8;
    const int tid = threadIdx.x;
    for (int i = tid; i < 512; i += 256) g1s[i] = g_g1[(size_t)row0 * 64 + i];
    __syncthreads();
#pragma unroll
    for (int cs = 0; cs < 4; cs++) {
        const int c = tid + cs * 256;
        float a[8];
#pragma unroll
        for (int r = 0; r < 8; r++) a[r] = 0.f;
#pragma unroll 4
        for (int k = 0; k < 64; k++) {
            float wv = Wg2[(size_t)k * DD + c];
#pragma unroll
            for (int r = 0; r < 8; r++) a[r] = fmaf(g1s[r * 64 + k], wv, a[r]);
        }
#pragma unroll
        for (int r = 0; r < 8; r++)
            rb[r * 1024 + c] = g_o[(size_t)(row0 + r) * DD + c] * sigmoidf_(a[r]);
    }
    __syncthreads();
    const int wr = tid >> 5, ln = tid & 31;
    float s = 0.f, s2 = 0.f;
#pragma unroll 8
    for (int i = 0; i < 32; i++) {
        float v = rb[wr * 1024 + ln + 32 * i];
        s += v; s2 = fmaf(v, v, s2);
    }
#pragma unroll
    for (int o = 16; o; o >>= 1) {
        s  += __shfl_xor_sync(0xffffffffu, s,  o);
        s2 += __shfl_xor_sync(0xffffffffu, s2, o);
    }
    const float mu = s * (1.f / 1024.f);
    const float rstd = rsqrtf(s2 * (1.f / 1024.f) - mu * mu + 1e-5f);
#pragma unroll 8
    for (int i = 0; i < 32; i++) {
        int c = ln + 32 * i;
        g_n[(size_t)(row0 + wr) * DD + c] = (rb[wr * 1024 + c] - mu) * rstd * nw[c];
    }
}

// -----------------------------------------------------------------------------
extern "C" void kernel_launch(void* const* d_in, const int* in_sizes, int n_in,
                              void* d_out, int out_size) {
    const float* x      = (const float*)d_in[0];
    const float* Wq     = (const float*)d_in[1];
    const float* Wk     = (const float*)d_in[2];
    const float* Wv     = (const float*)d_in[3];
    const float* Wgamma = (const float*)d_in[4];
    const float* Wf     = (const float*)d_in[5];
    const float* Wg1    = (const float*)d_in[6];
    const float* Wg2    = (const float*)d_in[7];
    const float* Wo     = (const float*)d_in[8];
    const float* norm_w = (const float*)d_in[9];
    float* out = (float*)d_out;

    cudaFuncSetAttribute(gemm_mma, cudaFuncAttributeMaxDynamicSharedMemorySize, GSMEM);

    __nv_bfloat16 *xh, *xl, *nh, *nl, *qh, *ql, *kh, *kl_, *vh, *vl, *oh, *ol, *sh, *sl;
    float *pq, *pk, *pv, *pn;
    cudaGetSymbolAddress((void**)&xh, g_xhi);  cudaGetSymbolAddress((void**)&xl, g_xlo);
    cudaGetSymbolAddress((void**)&nh, g_nhi);  cudaGetSymbolAddress((void**)&nl, g_nlo);
    cudaGetSymbolAddress((void**)&qh, g_wqhi); cudaGetSymbolAddress((void**)&ql, g_wqlo);
    cudaGetSymbolAddress((void**)&kh, g_wkhi); cudaGetSymbolAddress((void**)&kl_, g_wklo);
    cudaGetSymbolAddress((void**)&vh, g_wvhi); cudaGetSymbolAddress((void**)&vl, g_wvlo);
    cudaGetSymbolAddress((void**)&oh, g_wohi); cudaGetSymbolAddress((void**)&ol, g_wolo);
    cudaGetSymbolAddress((void**)&sh, g_wshi); cudaGetSymbolAddress((void**)&sl, g_wslo);
    cudaGetSymbolAddress((void**)&pq, g_q);    cudaGetSymbolAddress((void**)&pk, g_k);
    cudaGetSymbolAddress((void**)&pv, g_v);    cudaGetSymbolAddress((void**)&pn, g_n);

    conv_a<<<BN*DD/256, 256>>>(x, xh, xl);                       // 0
    conv_wT4<<<dim3(32, 32, 4), 256>>>(Wq, Wk, Wv, Wo,
        qh, ql, kh, kl_, vh, vl, oh, ol);                        // 1
    conv_small<<<128, 256>>>(Wgamma, Wf, Wg1);                   // 2

    dim3 gg(8, 32);
    gemm_mma<<<gg, 256, GSMEM>>>(xh, xl, qh, ql, pq, 1);         // 3
    gemm_mma<<<gg, 256, GSMEM>>>(xh, xl, kh, kl_, pk, 1);        // 4
    gemm_mma<<<gg, 256, GSMEM>>>(xh, xl, vh, vl, pv, 1);         // 5  <- ncu capture
    gemm_mma<<<dim3(1, 32), 256, GSMEM>>>(xh, xl, sh, sl, pq, 3);// 6

    l2norm_kernel<<<BN*HH/8, 256>>>();
    recur_kernel<<<128, 64>>>();
    gate_ln_kernel<<<BN/8, 256>>>(Wg2, norm_w);
    conv_a<<<BN*DD/256, 256>>>(pn, nh, nl);
    gemm_mma<<<gg, 256, GSMEM>>>(nh, nl, oh, ol, out, 0);
}